// round 1
// baseline (speedup 1.0000x reference)
#include <cuda_runtime.h>

#define SPAD 68
typedef unsigned long long u64;

// Scratch (device globals: allocation-free rule)
__device__ float g_qkv[32 * 3136 * 192];   // [B][N][3D]
__device__ float g_attn[32 * 3136 * 64];   // [B][N][D]

// ---------- packed f32x2 helpers ----------
__device__ __forceinline__ void f2fma(u64& d, u64 a, u64 b) {
    asm("fma.rn.f32x2 %0, %1, %2, %0;" : "+l"(d) : "l"(a), "l"(b));
}
__device__ __forceinline__ float f2sum(u64 v) {
    float lo, hi;
    asm("mov.b64 {%0,%1}, %2;" : "=f"(lo), "=f"(hi) : "l"(v));
    return lo + hi;
}

// ---------- register LayerNorm over 64 cols, 16-lane shuffle ----------
__device__ __forceinline__ void ln4x4(float acc[4][4],
                                      const float* __restrict__ g,
                                      const float* __restrict__ bb, int c0) {
    float4 gv = *(const float4*)(g + c0);
    float4 bv = *(const float4*)(bb + c0);
    float gg[4] = {gv.x, gv.y, gv.z, gv.w};
    float bbv[4] = {bv.x, bv.y, bv.z, bv.w};
#pragma unroll
    for (int i = 0; i < 4; i++) {
        float s = acc[i][0] + acc[i][1] + acc[i][2] + acc[i][3];
        float s2 = acc[i][0] * acc[i][0] + acc[i][1] * acc[i][1]
                 + acc[i][2] * acc[i][2] + acc[i][3] * acc[i][3];
#pragma unroll
        for (int o = 1; o < 16; o <<= 1) {
            s  += __shfl_xor_sync(0xffffffffu, s, o);
            s2 += __shfl_xor_sync(0xffffffffu, s2, o);
        }
        float mu = s * (1.0f / 64.0f);
        float var = s2 * (1.0f / 64.0f) - mu * mu;
        float rstd = rsqrtf(var + 1e-5f);
#pragma unroll
        for (int j = 0; j < 4; j++)
            acc[i][j] = (acc[i][j] - mu) * rstd * gg[j] + bbv[j];
    }
}

// =====================================================================
// Kernel 1: embed (x^T @ We + be) -> LN1 -> LN2 -> QKV GEMM
// grid (49, 32), block 256. Tile: 64 tokens.
// =====================================================================
__global__ __launch_bounds__(256) void k_embed_qkv(
    const float* __restrict__ x, const float* __restrict__ We, const float* __restrict__ be,
    const float* __restrict__ g1, const float* __restrict__ b1,
    const float* __restrict__ g2, const float* __restrict__ b2,
    const float* __restrict__ Wqkv, const float* __restrict__ bqkv)
{
    extern __shared__ float smem[];
    float* sx  = smem;           // [128][64]
    float* sWe = smem + 8192;    // [128][64]
    float* st  = smem + 16384;   // [64][SPAD]
    float* sWq = smem;           // reuse: [64][192] = 12288 floats <= 16384

    const int b   = blockIdx.y;
    const int n0  = blockIdx.x * 64;
    const int tid = threadIdx.x;
    const int tx = tid & 15, ty = tid >> 4;
    const int r0 = ty * 4, c0 = tx * 4;

    const float* xb = x + (size_t)b * 128 * 3136;
    for (int i = tid; i < 2048; i += 256) {
        int c = i >> 4, j4 = (i & 15) << 2;
        *(float4*)(sx + c * 64 + j4) = *(const float4*)(xb + (size_t)c * 3136 + n0 + j4);
    }
    for (int i = tid; i < 2048; i += 256) {
        int c = i >> 4, j4 = (i & 15) << 2;
        *(float4*)(sWe + c * 64 + j4) = *(const float4*)(We + c * 64 + j4);
    }
    __syncthreads();

    float acc[4][4];
#pragma unroll
    for (int i = 0; i < 4; i++)
#pragma unroll
        for (int j = 0; j < 4; j++) acc[i][j] = 0.f;

#pragma unroll 4
    for (int c = 0; c < 128; c++) {
        float4 av = *(const float4*)(sx + c * 64 + r0);
        float4 wv = *(const float4*)(sWe + c * 64 + c0);
        float a[4] = {av.x, av.y, av.z, av.w};
        float w[4] = {wv.x, wv.y, wv.z, wv.w};
#pragma unroll
        for (int i = 0; i < 4; i++)
#pragma unroll
            for (int j = 0; j < 4; j++) acc[i][j] += a[i] * w[j];
    }
    {
        float4 bev = *(const float4*)(be + c0);
        float bb[4] = {bev.x, bev.y, bev.z, bev.w};
#pragma unroll
        for (int i = 0; i < 4; i++)
#pragma unroll
            for (int j = 0; j < 4; j++) acc[i][j] += bb[j];
    }
    ln4x4(acc, g1, b1, c0);
    ln4x4(acc, g2, b2, c0);
#pragma unroll
    for (int i = 0; i < 4; i++)
        *(float4*)(st + (r0 + i) * SPAD + c0) =
            make_float4(acc[i][0], acc[i][1], acc[i][2], acc[i][3]);
    __syncthreads();

    for (int i = tid; i < 3072; i += 256)
        *(float4*)(sWq + i * 4) = *(const float4*)(Wqkv + i * 4);
    __syncthreads();

    const int cq0 = tx * 12;
    float acc2[4][12];
#pragma unroll
    for (int i = 0; i < 4; i++)
#pragma unroll
        for (int j = 0; j < 12; j++) acc2[i][j] = 0.f;

#pragma unroll 4
    for (int k = 0; k < 64; k++) {
        float a[4];
#pragma unroll
        for (int i = 0; i < 4; i++) a[i] = st[(r0 + i) * SPAD + k];
        float4 w0 = *(const float4*)(sWq + k * 192 + cq0);
        float4 w1 = *(const float4*)(sWq + k * 192 + cq0 + 4);
        float4 w2 = *(const float4*)(sWq + k * 192 + cq0 + 8);
        float w[12] = {w0.x, w0.y, w0.z, w0.w, w1.x, w1.y, w1.z, w1.w,
                       w2.x, w2.y, w2.z, w2.w};
#pragma unroll
        for (int i = 0; i < 4; i++)
#pragma unroll
            for (int j = 0; j < 12; j++) acc2[i][j] += a[i] * w[j];
    }
    {
        float4 q0 = *(const float4*)(bqkv + cq0);
        float4 q1 = *(const float4*)(bqkv + cq0 + 4);
        float4 q2 = *(const float4*)(bqkv + cq0 + 8);
        float bq[12] = {q0.x, q0.y, q0.z, q0.w, q1.x, q1.y, q1.z, q1.w,
                        q2.x, q2.y, q2.z, q2.w};
#pragma unroll
        for (int i = 0; i < 4; i++) {
            float* gout = g_qkv + (size_t)(b * 3136 + n0 + r0 + i) * 192 + cq0;
            *(float4*)(gout)     = make_float4(acc2[i][0] + bq[0],  acc2[i][1] + bq[1],
                                               acc2[i][2] + bq[2],  acc2[i][3] + bq[3]);
            *(float4*)(gout + 4) = make_float4(acc2[i][4] + bq[4],  acc2[i][5] + bq[5],
                                               acc2[i][6] + bq[6],  acc2[i][7] + bq[7]);
            *(float4*)(gout + 8) = make_float4(acc2[i][8] + bq[8],  acc2[i][9] + bq[9],
                                               acc2[i][10] + bq[10], acc2[i][11] + bq[11]);
        }
    }
}

// =====================================================================
// Kernel 2: flash attention, fp32, packed f32x2 FMA.
// grid (49, 32): 64-row q tile per CTA, stream 49 kv tiles of 64.
// =====================================================================
__global__ __launch_bounds__(256) void k_attn()
{
    extern __shared__ float smem[];
    float* sq  = smem;                // [64][SPAD]  (q * 0.125)
    float* sk  = sq  + 64 * SPAD;     // [64][SPAD]  (k rows)
    float* svt = sk  + 64 * SPAD;     // [64][SPAD]  (v transposed: [d][kk])
    float* sp  = svt + 64 * SPAD;     // [64][SPAD]  (softmax probs)

    const int b   = blockIdx.y;
    const int n0  = blockIdx.x * 64;
    const int tid = threadIdx.x;
    const int tx = tid & 15, ty = tid >> 4;
    const int r0 = ty * 4, c0 = tx * 4;

    const float* qb = g_qkv + (size_t)(b * 3136 + n0) * 192;
    for (int i = tid; i < 1024; i += 256) {
        int r = i >> 4, j4 = (i & 15) << 2;
        float4 v = *(const float4*)(qb + (size_t)r * 192 + j4);
        v.x *= 0.125f; v.y *= 0.125f; v.z *= 0.125f; v.w *= 0.125f;
        *(float4*)(sq + r * SPAD + j4) = v;
    }

    float m_[4], l_[4], O[4][4];
#pragma unroll
    for (int i = 0; i < 4; i++) {
        m_[i] = -1e30f; l_[i] = 0.f;
#pragma unroll
        for (int j = 0; j < 4; j++) O[i][j] = 0.f;
    }

    for (int t = 0; t < 49; ++t) {
        __syncthreads();   // protect sk/svt/sp reuse (and q load on iter 0)
        const float* kb = g_qkv + (size_t)(b * 3136 + t * 64) * 192 + 64;
        const float* vb = kb + 64;
        for (int i = tid; i < 1024; i += 256) {
            int r = i >> 4, j4 = (i & 15) << 2;
            *(float4*)(sk + r * SPAD + j4) = *(const float4*)(kb + (size_t)r * 192 + j4);
        }
        for (int i = tid; i < 1024; i += 256) {
            int d = i & 63, kk0 = (i >> 6) << 2;
            float v0 = vb[(size_t)(kk0 + 0) * 192 + d];
            float v1 = vb[(size_t)(kk0 + 1) * 192 + d];
            float v2 = vb[(size_t)(kk0 + 2) * 192 + d];
            float v3 = vb[(size_t)(kk0 + 3) * 192 + d];
            *(float4*)(svt + d * SPAD + kk0) = make_float4(v0, v1, v2, v3);
        }
        __syncthreads();

        // ---- S = (q*0.125) @ k^T  (packed over d) ----
        u64 S2[4][4];
#pragma unroll
        for (int i = 0; i < 4; i++)
#pragma unroll
            for (int j = 0; j < 4; j++) S2[i][j] = 0ULL;

#pragma unroll 4
        for (int d4 = 0; d4 < 64; d4 += 4) {
            ulonglong2 a[4], kv[4];
#pragma unroll
            for (int i = 0; i < 4; i++)
                a[i] = *(const ulonglong2*)(sq + (r0 + i) * SPAD + d4);
#pragma unroll
            for (int j = 0; j < 4; j++)
                kv[j] = *(const ulonglong2*)(sk + (c0 + j) * SPAD + d4);
#pragma unroll
            for (int i = 0; i < 4; i++)
#pragma unroll
                for (int j = 0; j < 4; j++) {
                    f2fma(S2[i][j], a[i].x, kv[j].x);
                    f2fma(S2[i][j], a[i].y, kv[j].y);
                }
        }

        // ---- online softmax ----
        float fct[4];
#pragma unroll
        for (int i = 0; i < 4; i++) {
            float s0 = f2sum(S2[i][0]), s1 = f2sum(S2[i][1]);
            float s2 = f2sum(S2[i][2]), s3 = f2sum(S2[i][3]);
            float mx = fmaxf(fmaxf(s0, s1), fmaxf(s2, s3));
#pragma unroll
            for (int o = 1; o < 16; o <<= 1)
                mx = fmaxf(mx, __shfl_xor_sync(0xffffffffu, mx, o));
            float mn = fmaxf(m_[i], mx);
            fct[i] = __expf(m_[i] - mn);
            float p0 = __expf(s0 - mn), p1 = __expf(s1 - mn);
            float p2 = __expf(s2 - mn), p3 = __expf(s3 - mn);
            float rs = p0 + p1 + p2 + p3;
#pragma unroll
            for (int o = 1; o < 16; o <<= 1)
                rs += __shfl_xor_sync(0xffffffffu, rs, o);
            l_[i] = l_[i] * fct[i] + rs;
            m_[i] = mn;
            *(float4*)(sp + (r0 + i) * SPAD + c0) = make_float4(p0, p1, p2, p3);
        }
        __syncthreads();

        // ---- O = O*f + P @ V  (packed over kk via v-transpose) ----
        u64 Op[4][4];
#pragma unroll
        for (int i = 0; i < 4; i++)
#pragma unroll
            for (int j = 0; j < 4; j++) Op[i][j] = 0ULL;

#pragma unroll 4
        for (int k4 = 0; k4 < 64; k4 += 4) {
            ulonglong2 pa[4], va[4];
#pragma unroll
            for (int i = 0; i < 4; i++)
                pa[i] = *(const ulonglong2*)(sp + (r0 + i) * SPAD + k4);
#pragma unroll
            for (int j = 0; j < 4; j++)
                va[j] = *(const ulonglong2*)(svt + (c0 + j) * SPAD + k4);
#pragma unroll
            for (int i = 0; i < 4; i++)
#pragma unroll
                for (int j = 0; j < 4; j++) {
                    f2fma(Op[i][j], pa[i].x, va[j].x);
                    f2fma(Op[i][j], pa[i].y, va[j].y);
                }
        }
#pragma unroll
        for (int i = 0; i < 4; i++)
#pragma unroll
            for (int j = 0; j < 4; j++)
                O[i][j] = O[i][j] * fct[i] + f2sum(Op[i][j]);
    }

    float* ob = g_attn + (size_t)(b * 3136 + n0) * 64;
#pragma unroll
    for (int i = 0; i < 4; i++) {
        float inv = 1.0f / l_[i];
        *(float4*)(ob + (size_t)(r0 + i) * 64 + c0) =
            make_float4(O[i][0] * inv, O[i][1] * inv, O[i][2] * inv, O[i][3] * inv);
    }
}

// =====================================================================
// Kernel 3: proj + LN + GELU MLP + channel mean
// =====================================================================
__global__ __launch_bounds__(256) void k_mlp(
    const float* __restrict__ Wp, const float* __restrict__ bp,
    const float* __restrict__ gm, const float* __restrict__ bm,
    const float* __restrict__ W1, const float* __restrict__ bm1,
    const float* __restrict__ W2, const float* __restrict__ bm2,
    float* __restrict__ out)
{
    extern __shared__ float smem[];
    float* sA  = smem;                // [64][SPAD]
    float* sB  = sA + 64 * SPAD;      // [64][SPAD]
    float* sWp = sB + 64 * SPAD;      // [64][64]
    float* sW1 = sWp + 4096;
    float* sW2 = sW1 + 4096;

    const int b   = blockIdx.y;
    const int n0  = blockIdx.x * 64;
    const int tid = threadIdx.x;
    const int tx = tid & 15, ty = tid >> 4;
    const int r0 = ty * 4, c0 = tx * 4;

    const float* ain = g_attn + (size_t)(b * 3136 + n0) * 64;
    for (int i = tid; i < 1024; i += 256) {
        int r = i >> 4, j4 = (i & 15) << 2;
        *(float4*)(sA + r * SPAD + j4) = *(const float4*)(ain + (size_t)r * 64 + j4);
    }
    for (int i = tid; i < 1024; i += 256) *(float4*)(sWp + i * 4) = *(const float4*)(Wp + i * 4);
    for (int i = tid; i < 1024; i += 256) *(float4*)(sW1 + i * 4) = *(const float4*)(W1 + i * 4);
    for (int i = tid; i < 1024; i += 256) *(float4*)(sW2 + i * 4) = *(const float4*)(W2 + i * 4);
    __syncthreads();

    float acc[4][4];
    // ---- t = A @ Wp + bp ----
#pragma unroll
    for (int i = 0; i < 4; i++)
#pragma unroll
        for (int j = 0; j < 4; j++) acc[i][j] = 0.f;
#pragma unroll 4
    for (int k = 0; k < 64; k++) {
        float a[4];
#pragma unroll
        for (int i = 0; i < 4; i++) a[i] = sA[(r0 + i) * SPAD + k];
        float4 w = *(const float4*)(sWp + k * 64 + c0);
        float wv[4] = {w.x, w.y, w.z, w.w};
#pragma unroll
        for (int i = 0; i < 4; i++)
#pragma unroll
            for (int j = 0; j < 4; j++) acc[i][j] += a[i] * wv[j];
    }
    {
        float4 bv = *(const float4*)(bp + c0);
        float bb[4] = {bv.x, bv.y, bv.z, bv.w};
#pragma unroll
        for (int i = 0; i < 4; i++)
#pragma unroll
            for (int j = 0; j < 4; j++) acc[i][j] += bb[j];
    }
    ln4x4(acc, gm, bm, c0);
#pragma unroll
    for (int i = 0; i < 4; i++)
        *(float4*)(sB + (r0 + i) * SPAD + c0) =
            make_float4(acc[i][0], acc[i][1], acc[i][2], acc[i][3]);
    __syncthreads();

    // ---- h1 = gelu(B @ W1 + bm1) ----
#pragma unroll
    for (int i = 0; i < 4; i++)
#pragma unroll
        for (int j = 0; j < 4; j++) acc[i][j] = 0.f;
#pragma unroll 4
    for (int k = 0; k < 64; k++) {
        float a[4];
#pragma unroll
        for (int i = 0; i < 4; i++) a[i] = sB[(r0 + i) * SPAD + k];
        float4 w = *(const float4*)(sW1 + k * 64 + c0);
        float wv[4] = {w.x, w.y, w.z, w.w};
#pragma unroll
        for (int i = 0; i < 4; i++)
#pragma unroll
            for (int j = 0; j < 4; j++) acc[i][j] += a[i] * wv[j];
    }
    {
        float4 bv = *(const float4*)(bm1 + c0);
        float bb[4] = {bv.x, bv.y, bv.z, bv.w};
#pragma unroll
        for (int i = 0; i < 4; i++)
#pragma unroll
            for (int j = 0; j < 4; j++) {
                float v = acc[i][j] + bb[j];
                acc[i][j] = 0.5f * v * (1.0f + erff(v * 0.70710678118654752f));
            }
    }
#pragma unroll
    for (int i = 0; i < 4; i++)
        *(float4*)(sA + (r0 + i) * SPAD + c0) =
            make_float4(acc[i][0], acc[i][1], acc[i][2], acc[i][3]);
    __syncthreads();

    // ---- h2 = h1 @ W2 + bm2 ; out = rowmean(h2) ----
#pragma unroll
    for (int i = 0; i < 4; i++)
#pragma unroll
        for (int j = 0; j < 4; j++) acc[i][j] = 0.f;
#pragma unroll 4
    for (int k = 0; k < 64; k++) {
        float a[4];
#pragma unroll
        for (int i = 0; i < 4; i++) a[i] = sA[(r0 + i) * SPAD + k];
        float4 w = *(const float4*)(sW2 + k * 64 + c0);
        float wv[4] = {w.x, w.y, w.z, w.w};
#pragma unroll
        for (int i = 0; i < 4; i++)
#pragma unroll
            for (int j = 0; j < 4; j++) acc[i][j] += a[i] * wv[j];
    }
    {
        float4 bv = *(const float4*)(bm2 + c0);
        float bb[4] = {bv.x, bv.y, bv.z, bv.w};
#pragma unroll
        for (int i = 0; i < 4; i++) {
            float s = (acc[i][0] + bb[0]) + (acc[i][1] + bb[1])
                    + (acc[i][2] + bb[2]) + (acc[i][3] + bb[3]);
#pragma unroll
            for (int o = 1; o < 16; o <<= 1)
                s += __shfl_xor_sync(0xffffffffu, s, o);
            if (tx == 0)
                out[(size_t)b * 3136 + n0 + r0 + i] = s * (1.0f / 64.0f);
        }
    }
}

// =====================================================================
extern "C" void kernel_launch(void* const* d_in, const int* in_sizes, int n_in,
                              void* d_out, int out_size)
{
    const float* x    = (const float*)d_in[0];
    const float* We   = (const float*)d_in[1];
    const float* be   = (const float*)d_in[2];
    const float* g1   = (const float*)d_in[3];
    const float* b1   = (const float*)d_in[4];
    const float* g2   = (const float*)d_in[5];
    const float* b2   = (const float*)d_in[6];
    const float* Wqkv = (const float*)d_in[7];
    const float* bqkv = (const float*)d_in[8];
    const float* Wp   = (const float*)d_in[9];
    const float* bp   = (const float*)d_in[10];
    const float* gm   = (const float*)d_in[11];
    const float* bm   = (const float*)d_in[12];
    const float* W1   = (const float*)d_in[13];
    const float* bm1  = (const float*)d_in[14];
    const float* W2   = (const float*)d_in[15];
    const float* bm2  = (const float*)d_in[16];
    float* out = (float*)d_out;

    const int SM1 = (8192 + 8192 + 64 * SPAD) * 4;           // 82,944 B
    const int SM2 = 4 * 64 * SPAD * 4;                        // 69,632 B
    const int SM3 = (2 * 64 * SPAD + 3 * 4096) * 4;           // 83,968 B

    (void)cudaFuncSetAttribute(k_embed_qkv, cudaFuncAttributeMaxDynamicSharedMemorySize, SM1);
    (void)cudaFuncSetAttribute(k_attn,      cudaFuncAttributeMaxDynamicSharedMemorySize, SM2);
    (void)cudaFuncSetAttribute(k_mlp,       cudaFuncAttributeMaxDynamicSharedMemorySize, SM3);

    dim3 grid(49, 32);
    k_embed_qkv<<<grid, 256, SM1>>>(x, We, be, g1, b1, g2, b2, Wqkv, bqkv);
    k_attn<<<grid, 256, SM2>>>();
    k_mlp<<<grid, 256, SM3>>>(Wp, bp, gm, bm, W1, bm1, W2, bm2, out);
}

// round 3
// speedup vs baseline: 4.9355x; 4.9355x over previous
#include <cuda_runtime.h>

#define SPAD 68
#define SP 72          // attn smem row stride (bank-conflict-free fragments)
typedef unsigned long long u64;
typedef unsigned int u32;

extern __shared__ char smem_raw[];   // single extern-shared symbol for all kernels

// Scratch (device globals: allocation-free rule)
__device__ float g_qkv[32 * 3136 * 192];   // [B][N][3D]
__device__ float g_attn[32 * 3136 * 64];   // [B][N][D]

// ---------- tf32 helpers ----------
__device__ __forceinline__ u32 f2tf32(float x) {
    u32 r;
    asm("cvt.rna.tf32.f32 %0, %1;" : "=r"(r) : "f"(x));
    return r;
}
__device__ __forceinline__ void mma_tf32(float c[4], u32 a0, u32 a1, u32 a2, u32 a3,
                                         u32 b0, u32 b1) {
    asm volatile(
        "mma.sync.aligned.m16n8k8.row.col.f32.tf32.tf32.f32 "
        "{%0,%1,%2,%3}, {%4,%5,%6,%7}, {%8,%9}, {%0,%1,%2,%3};"
        : "+f"(c[0]), "+f"(c[1]), "+f"(c[2]), "+f"(c[3])
        : "r"(a0), "r"(a1), "r"(a2), "r"(a3), "r"(b0), "r"(b1));
}

// ---------- register LayerNorm over 64 cols, 16-lane shuffle ----------
__device__ __forceinline__ void ln4x4(float acc[4][4],
                                      const float* __restrict__ g,
                                      const float* __restrict__ bb, int c0) {
    float4 gv = *(const float4*)(g + c0);
    float4 bv = *(const float4*)(bb + c0);
    float gg[4] = {gv.x, gv.y, gv.z, gv.w};
    float bbv[4] = {bv.x, bv.y, bv.z, bv.w};
#pragma unroll
    for (int i = 0; i < 4; i++) {
        float s = acc[i][0] + acc[i][1] + acc[i][2] + acc[i][3];
        float s2 = acc[i][0] * acc[i][0] + acc[i][1] * acc[i][1]
                 + acc[i][2] * acc[i][2] + acc[i][3] * acc[i][3];
#pragma unroll
        for (int o = 1; o < 16; o <<= 1) {
            s  += __shfl_xor_sync(0xffffffffu, s, o);
            s2 += __shfl_xor_sync(0xffffffffu, s2, o);
        }
        float mu = s * (1.0f / 64.0f);
        float var = s2 * (1.0f / 64.0f) - mu * mu;
        float rstd = rsqrtf(var + 1e-5f);
#pragma unroll
        for (int j = 0; j < 4; j++)
            acc[i][j] = (acc[i][j] - mu) * rstd * gg[j] + bbv[j];
    }
}

// =====================================================================
// Kernel 1: embed (x^T @ We + be) -> LN1 -> LN2 -> QKV GEMM
// =====================================================================
__global__ __launch_bounds__(256) void k_embed_qkv(
    const float* __restrict__ x, const float* __restrict__ We, const float* __restrict__ be,
    const float* __restrict__ g1, const float* __restrict__ b1,
    const float* __restrict__ g2, const float* __restrict__ b2,
    const float* __restrict__ Wqkv, const float* __restrict__ bqkv)
{
    float* smem = (float*)smem_raw;
    float* sx  = smem;           // [128][64]
    float* sWe = smem + 8192;    // [128][64]
    float* st  = smem + 16384;   // [64][SPAD]
    float* sWq = smem;           // reuse

    const int b   = blockIdx.y;
    const int n0  = blockIdx.x * 64;
    const int tid = threadIdx.x;
    const int tx = tid & 15, ty = tid >> 4;
    const int r0 = ty * 4, c0 = tx * 4;

    const float* xb = x + (size_t)b * 128 * 3136;
    for (int i = tid; i < 2048; i += 256) {
        int c = i >> 4, j4 = (i & 15) << 2;
        *(float4*)(sx + c * 64 + j4) = *(const float4*)(xb + (size_t)c * 3136 + n0 + j4);
    }
    for (int i = tid; i < 2048; i += 256) {
        int c = i >> 4, j4 = (i & 15) << 2;
        *(float4*)(sWe + c * 64 + j4) = *(const float4*)(We + c * 64 + j4);
    }
    __syncthreads();

    float acc[4][4];
#pragma unroll
    for (int i = 0; i < 4; i++)
#pragma unroll
        for (int j = 0; j < 4; j++) acc[i][j] = 0.f;

#pragma unroll 4
    for (int c = 0; c < 128; c++) {
        float4 av = *(const float4*)(sx + c * 64 + r0);
        float4 wv = *(const float4*)(sWe + c * 64 + c0);
        float a[4] = {av.x, av.y, av.z, av.w};
        float w[4] = {wv.x, wv.y, wv.z, wv.w};
#pragma unroll
        for (int i = 0; i < 4; i++)
#pragma unroll
            for (int j = 0; j < 4; j++) acc[i][j] += a[i] * w[j];
    }
    {
        float4 bev = *(const float4*)(be + c0);
        float bb[4] = {bev.x, bev.y, bev.z, bev.w};
#pragma unroll
        for (int i = 0; i < 4; i++)
#pragma unroll
            for (int j = 0; j < 4; j++) acc[i][j] += bb[j];
    }
    ln4x4(acc, g1, b1, c0);
    ln4x4(acc, g2, b2, c0);
#pragma unroll
    for (int i = 0; i < 4; i++)
        *(float4*)(st + (r0 + i) * SPAD + c0) =
            make_float4(acc[i][0], acc[i][1], acc[i][2], acc[i][3]);
    __syncthreads();

    for (int i = tid; i < 3072; i += 256)
        *(float4*)(sWq + i * 4) = *(const float4*)(Wqkv + i * 4);
    __syncthreads();

    const int cq0 = tx * 12;
    float acc2[4][12];
#pragma unroll
    for (int i = 0; i < 4; i++)
#pragma unroll
        for (int j = 0; j < 12; j++) acc2[i][j] = 0.f;

#pragma unroll 4
    for (int k = 0; k < 64; k++) {
        float a[4];
#pragma unroll
        for (int i = 0; i < 4; i++) a[i] = st[(r0 + i) * SPAD + k];
        float4 w0 = *(const float4*)(sWq + k * 192 + cq0);
        float4 w1 = *(const float4*)(sWq + k * 192 + cq0 + 4);
        float4 w2 = *(const float4*)(sWq + k * 192 + cq0 + 8);
        float w[12] = {w0.x, w0.y, w0.z, w0.w, w1.x, w1.y, w1.z, w1.w,
                       w2.x, w2.y, w2.z, w2.w};
#pragma unroll
        for (int i = 0; i < 4; i++)
#pragma unroll
            for (int j = 0; j < 12; j++) acc2[i][j] += a[i] * w[j];
    }
    {
        float4 q0 = *(const float4*)(bqkv + cq0);
        float4 q1 = *(const float4*)(bqkv + cq0 + 4);
        float4 q2 = *(const float4*)(bqkv + cq0 + 8);
        float bq[12] = {q0.x, q0.y, q0.z, q0.w, q1.x, q1.y, q1.z, q1.w,
                        q2.x, q2.y, q2.z, q2.w};
#pragma unroll
        for (int i = 0; i < 4; i++) {
            float* gout = g_qkv + (size_t)(b * 3136 + n0 + r0 + i) * 192 + cq0;
            *(float4*)(gout)     = make_float4(acc2[i][0] + bq[0],  acc2[i][1] + bq[1],
                                               acc2[i][2] + bq[2],  acc2[i][3] + bq[3]);
            *(float4*)(gout + 4) = make_float4(acc2[i][4] + bq[4],  acc2[i][5] + bq[5],
                                               acc2[i][6] + bq[6],  acc2[i][7] + bq[7]);
            *(float4*)(gout + 8) = make_float4(acc2[i][8] + bq[8],  acc2[i][9] + bq[9],
                                               acc2[i][10] + bq[10], acc2[i][11] + bq[11]);
        }
    }
}

// =====================================================================
// Kernel 2: flash attention with tf32 mma.sync tensor cores.
// grid (49, 32), 128 threads (4 warps). Warp w owns q rows [w*16, w*16+16).
// SMEM tiles hold tf32-rounded bits; stride SP=72 -> conflict-free frags.
// =====================================================================
__global__ __launch_bounds__(128) void k_attn()
{
    u32* smem = (u32*)smem_raw;
    u32* sq = smem;               // [64][SP]  q*0.125, tf32 bits
    u32* sk = sq + 64 * SP;       // [64][SP]  k rows (token-major)
    u32* sv = sk + 64 * SP;       // [64][SP]  v rows (token-major)
    u32* sp = sv + 64 * SP;       // [64][SP]  probs (tf32), warp-private rows

    const int b    = blockIdx.y;
    const int nq0  = blockIdx.x * 64;
    const int tid  = threadIdx.x;
    const int lane = tid & 31;
    const int w    = tid >> 5;
    const int m0   = w * 16;
    const int qr   = lane >> 2;   // 0..7
    const int qc   = lane & 3;    // 0..3

    // ---- load Q tile (scaled by 0.125, rounded to tf32) ----
    {
        const float* qb = g_qkv + (size_t)(b * 3136 + nq0) * 192;
#pragma unroll
        for (int i = 0; i < 8; i++) {
            int idx = tid + i * 128;
            int r = idx >> 4, c4 = (idx & 15) << 2;
            float4 v = *(const float4*)(qb + (size_t)r * 192 + c4);
            u32* d = sq + r * SP + c4;
            d[0] = f2tf32(v.x * 0.125f); d[1] = f2tf32(v.y * 0.125f);
            d[2] = f2tf32(v.z * 0.125f); d[3] = f2tf32(v.w * 0.125f);
        }
    }

    float O[8][4];
#pragma unroll
    for (int nt = 0; nt < 8; nt++)
#pragma unroll
        for (int j = 0; j < 4; j++) O[nt][j] = 0.f;
    float m1 = -1e30f, m2 = -1e30f, l1 = 0.f, l2 = 0.f;

    for (int t = 0; t < 49; ++t) {
        __syncthreads();   // previous tile's S/PV reads of sk/sv done
        {
            const float* kb = g_qkv + (size_t)(b * 3136 + t * 64) * 192 + 64;
            const float* vb = kb + 64;
#pragma unroll
            for (int i = 0; i < 8; i++) {
                int idx = tid + i * 128;
                int r = idx >> 4, c4 = (idx & 15) << 2;
                float4 kv = *(const float4*)(kb + (size_t)r * 192 + c4);
                float4 vv = *(const float4*)(vb + (size_t)r * 192 + c4);
                u32* dk = sk + r * SP + c4;
                u32* dv = sv + r * SP + c4;
                dk[0] = f2tf32(kv.x); dk[1] = f2tf32(kv.y);
                dk[2] = f2tf32(kv.z); dk[3] = f2tf32(kv.w);
                dv[0] = f2tf32(vv.x); dv[1] = f2tf32(vv.y);
                dv[2] = f2tf32(vv.z); dv[3] = f2tf32(vv.w);
            }
        }
        __syncthreads();

        // ---- S = Qs @ K^T : warp tile m16 n64, k=64 (8 k-steps) ----
        float S[8][4];
#pragma unroll
        for (int nt = 0; nt < 8; nt++)
#pragma unroll
            for (int j = 0; j < 4; j++) S[nt][j] = 0.f;

#pragma unroll
        for (int kk = 0; kk < 8; kk++) {
            int k0 = kk * 8;
            u32 a0 = sq[(m0 + qr) * SP + k0 + qc];
            u32 a1 = sq[(m0 + 8 + qr) * SP + k0 + qc];
            u32 a2 = sq[(m0 + qr) * SP + k0 + 4 + qc];
            u32 a3 = sq[(m0 + 8 + qr) * SP + k0 + 4 + qc];
#pragma unroll
            for (int nt = 0; nt < 8; nt++) {
                int n0 = nt * 8;
                u32 b0 = sk[(n0 + qr) * SP + k0 + qc];
                u32 b1 = sk[(n0 + qr) * SP + k0 + 4 + qc];
                mma_tf32(S[nt], a0, a1, a2, a3, b0, b1);
            }
        }

        // ---- online softmax (rows r1 = m0+qr, r2 = r1+8) ----
        float mx1 = -1e30f, mx2 = -1e30f;
#pragma unroll
        for (int nt = 0; nt < 8; nt++) {
            mx1 = fmaxf(mx1, fmaxf(S[nt][0], S[nt][1]));
            mx2 = fmaxf(mx2, fmaxf(S[nt][2], S[nt][3]));
        }
#pragma unroll
        for (int o = 1; o < 4; o <<= 1) {
            mx1 = fmaxf(mx1, __shfl_xor_sync(0xffffffffu, mx1, o));
            mx2 = fmaxf(mx2, __shfl_xor_sync(0xffffffffu, mx2, o));
        }
        float mn1 = fmaxf(m1, mx1), mn2 = fmaxf(m2, mx2);
        float fct1 = __expf(m1 - mn1), fct2 = __expf(m2 - mn2);
        m1 = mn1; m2 = mn2;

        float rs1 = 0.f, rs2 = 0.f;
#pragma unroll
        for (int nt = 0; nt < 8; nt++) {
            int n0 = nt * 8;
            float p0 = __expf(S[nt][0] - mn1);
            float p1 = __expf(S[nt][1] - mn1);
            float p2 = __expf(S[nt][2] - mn2);
            float p3 = __expf(S[nt][3] - mn2);
            rs1 += p0 + p1; rs2 += p2 + p3;
            uint2 w1v = make_uint2(f2tf32(p0), f2tf32(p1));
            uint2 w2v = make_uint2(f2tf32(p2), f2tf32(p3));
            *(uint2*)(sp + (m0 + qr) * SP + n0 + 2 * qc) = w1v;
            *(uint2*)(sp + (m0 + 8 + qr) * SP + n0 + 2 * qc) = w2v;
        }
#pragma unroll
        for (int o = 1; o < 4; o <<= 1) {
            rs1 += __shfl_xor_sync(0xffffffffu, rs1, o);
            rs2 += __shfl_xor_sync(0xffffffffu, rs2, o);
        }
        l1 = l1 * fct1 + rs1;
        l2 = l2 * fct2 + rs2;

        // rescale O before accumulating this tile
#pragma unroll
        for (int nt = 0; nt < 8; nt++) {
            O[nt][0] *= fct1; O[nt][1] *= fct1;
            O[nt][2] *= fct2; O[nt][3] *= fct2;
        }
        __syncwarp();   // sp rows are warp-private; order STS -> LDS

        // ---- O += P @ V : m16 n64, k=64 ----
#pragma unroll
        for (int kk = 0; kk < 8; kk++) {
            int k0 = kk * 8;
            u32 a0 = sp[(m0 + qr) * SP + k0 + qc];
            u32 a1 = sp[(m0 + 8 + qr) * SP + k0 + qc];
            u32 a2 = sp[(m0 + qr) * SP + k0 + 4 + qc];
            u32 a3 = sp[(m0 + 8 + qr) * SP + k0 + 4 + qc];
#pragma unroll
            for (int nt = 0; nt < 8; nt++) {
                int n0 = nt * 8;
                u32 b0 = sv[(k0 + qc) * SP + n0 + qr];
                u32 b1 = sv[(k0 + 4 + qc) * SP + n0 + qr];
                mma_tf32(O[nt], a0, a1, a2, a3, b0, b1);
            }
        }
    }

    // ---- epilogue: O /= l, write [64][64] block ----
    float inv1 = 1.0f / l1, inv2 = 1.0f / l2;
    float* ob = g_attn + (size_t)(b * 3136 + nq0) * 64;
#pragma unroll
    for (int nt = 0; nt < 8; nt++) {
        int n0 = nt * 8 + 2 * qc;
        *(float2*)(ob + (size_t)(m0 + qr) * 64 + n0) =
            make_float2(O[nt][0] * inv1, O[nt][1] * inv1);
        *(float2*)(ob + (size_t)(m0 + 8 + qr) * 64 + n0) =
            make_float2(O[nt][2] * inv2, O[nt][3] * inv2);
    }
}

// =====================================================================
// Kernel 3: proj + LN + GELU MLP + channel mean
// =====================================================================
__global__ __launch_bounds__(256) void k_mlp(
    const float* __restrict__ Wp, const float* __restrict__ bp,
    const float* __restrict__ gm, const float* __restrict__ bm,
    const float* __restrict__ W1, const float* __restrict__ bm1,
    const float* __restrict__ W2, const float* __restrict__ bm2,
    float* __restrict__ out)
{
    float* smemf = (float*)smem_raw;
    float* sA  = smemf;               // [64][SPAD]
    float* sB  = sA + 64 * SPAD;      // [64][SPAD]
    float* sWp = sB + 64 * SPAD;      // [64][64]
    float* sW1 = sWp + 4096;
    float* sW2 = sW1 + 4096;

    const int b   = blockIdx.y;
    const int n0  = blockIdx.x * 64;
    const int tid = threadIdx.x;
    const int tx = tid & 15, ty = tid >> 4;
    const int r0 = ty * 4, c0 = tx * 4;

    const float* ain = g_attn + (size_t)(b * 3136 + n0) * 64;
    for (int i = tid; i < 1024; i += 256) {
        int r = i >> 4, j4 = (i & 15) << 2;
        *(float4*)(sA + r * SPAD + j4) = *(const float4*)(ain + (size_t)r * 64 + j4);
    }
    for (int i = tid; i < 1024; i += 256) *(float4*)(sWp + i * 4) = *(const float4*)(Wp + i * 4);
    for (int i = tid; i < 1024; i += 256) *(float4*)(sW1 + i * 4) = *(const float4*)(W1 + i * 4);
    for (int i = tid; i < 1024; i += 256) *(float4*)(sW2 + i * 4) = *(const float4*)(W2 + i * 4);
    __syncthreads();

    float acc[4][4];
#pragma unroll
    for (int i = 0; i < 4; i++)
#pragma unroll
        for (int j = 0; j < 4; j++) acc[i][j] = 0.f;
#pragma unroll 4
    for (int k = 0; k < 64; k++) {
        float a[4];
#pragma unroll
        for (int i = 0; i < 4; i++) a[i] = sA[(r0 + i) * SPAD + k];
        float4 w = *(const float4*)(sWp + k * 64 + c0);
        float wv[4] = {w.x, w.y, w.z, w.w};
#pragma unroll
        for (int i = 0; i < 4; i++)
#pragma unroll
            for (int j = 0; j < 4; j++) acc[i][j] += a[i] * wv[j];
    }
    {
        float4 bv = *(const float4*)(bp + c0);
        float bb[4] = {bv.x, bv.y, bv.z, bv.w};
#pragma unroll
        for (int i = 0; i < 4; i++)
#pragma unroll
            for (int j = 0; j < 4; j++) acc[i][j] += bb[j];
    }
    ln4x4(acc, gm, bm, c0);
#pragma unroll
    for (int i = 0; i < 4; i++)
        *(float4*)(sB + (r0 + i) * SPAD + c0) =
            make_float4(acc[i][0], acc[i][1], acc[i][2], acc[i][3]);
    __syncthreads();

#pragma unroll
    for (int i = 0; i < 4; i++)
#pragma unroll
        for (int j = 0; j < 4; j++) acc[i][j] = 0.f;
#pragma unroll 4
    for (int k = 0; k < 64; k++) {
        float a[4];
#pragma unroll
        for (int i = 0; i < 4; i++) a[i] = sB[(r0 + i) * SPAD + k];
        float4 wv4 = *(const float4*)(sW1 + k * 64 + c0);
        float wv[4] = {wv4.x, wv4.y, wv4.z, wv4.w};
#pragma unroll
        for (int i = 0; i < 4; i++)
#pragma unroll
            for (int j = 0; j < 4; j++) acc[i][j] += a[i] * wv[j];
    }
    {
        float4 bv = *(const float4*)(bm1 + c0);
        float bb[4] = {bv.x, bv.y, bv.z, bv.w};
#pragma unroll
        for (int i = 0; i < 4; i++)
#pragma unroll
            for (int j = 0; j < 4; j++) {
                float v = acc[i][j] + bb[j];
                acc[i][j] = 0.5f * v * (1.0f + erff(v * 0.70710678118654752f));
            }
    }
#pragma unroll
    for (int i = 0; i < 4; i++)
        *(float4*)(sA + (r0 + i) * SPAD + c0) =
            make_float4(acc[i][0], acc[i][1], acc[i][2], acc[i][3]);
    __syncthreads();

#pragma unroll
    for (int i = 0; i < 4; i++)
#pragma unroll
        for (int j = 0; j < 4; j++) acc[i][j] = 0.f;
#pragma unroll 4
    for (int k = 0; k < 64; k++) {
        float a[4];
#pragma unroll
        for (int i = 0; i < 4; i++) a[i] = sA[(r0 + i) * SPAD + k];
        float4 wv4 = *(const float4*)(sW2 + k * 64 + c0);
        float wv[4] = {wv4.x, wv4.y, wv4.z, wv4.w};
#pragma unroll
        for (int i = 0; i < 4; i++)
#pragma unroll
            for (int j = 0; j < 4; j++) acc[i][j] += a[i] * wv[j];
    }
    {
        float4 bv = *(const float4*)(bm2 + c0);
        float bb[4] = {bv.x, bv.y, bv.z, bv.w};
#pragma unroll
        for (int i = 0; i < 4; i++) {
            float s = (acc[i][0] + bb[0]) + (acc[i][1] + bb[1])
                    + (acc[i][2] + bb[2]) + (acc[i][3] + bb[3]);
#pragma unroll
            for (int o = 1; o < 16; o <<= 1)
                s += __shfl_xor_sync(0xffffffffu, s, o);
            if (tx == 0)
                out[(size_t)b * 3136 + n0 + r0 + i] = s * (1.0f / 64.0f);
        }
    }
}

// =====================================================================
extern "C" void kernel_launch(void* const* d_in, const int* in_sizes, int n_in,
                              void* d_out, int out_size)
{
    const float* x    = (const float*)d_in[0];
    const float* We   = (const float*)d_in[1];
    const float* be   = (const float*)d_in[2];
    const float* g1   = (const float*)d_in[3];
    const float* b1   = (const float*)d_in[4];
    const float* g2   = (const float*)d_in[5];
    const float* b2   = (const float*)d_in[6];
    const float* Wqkv = (const float*)d_in[7];
    const float* bqkv = (const float*)d_in[8];
    const float* Wp   = (const float*)d_in[9];
    const float* bp   = (const float*)d_in[10];
    const float* gm   = (const float*)d_in[11];
    const float* bm   = (const float*)d_in[12];
    const float* W1   = (const float*)d_in[13];
    const float* bm1  = (const float*)d_in[14];
    const float* W2   = (const float*)d_in[15];
    const float* bm2  = (const float*)d_in[16];
    float* out = (float*)d_out;

    const int SM1 = (8192 + 8192 + 64 * SPAD) * 4;   // 82,944 B
    const int SM2 = 4 * 64 * SP * 4;                 // 73,728 B
    const int SM3 = (2 * 64 * SPAD + 3 * 4096) * 4;  // 83,968 B

    (void)cudaFuncSetAttribute(k_embed_qkv, cudaFuncAttributeMaxDynamicSharedMemorySize, SM1);
    (void)cudaFuncSetAttribute(k_attn,      cudaFuncAttributeMaxDynamicSharedMemorySize, SM2);
    (void)cudaFuncSetAttribute(k_mlp,       cudaFuncAttributeMaxDynamicSharedMemorySize, SM3);

    dim3 grid(49, 32);
    k_embed_qkv<<<grid, 256, SM1>>>(x, We, be, g1, b1, g2, b2, Wqkv, bqkv);
    k_attn<<<grid, 128, SM2>>>();
    k_mlp<<<grid, 256, SM3>>>(Wp, bp, gm, bm, W1, bm1, W2, bm2, out);
}